// round 5
// baseline (speedup 1.0000x reference)
#include <cuda_runtime.h>
#include <cuda_bf16.h>
#include <cstdint>

// ---------------- problem constants ----------------
#define D_ 2048
#define B_ 4
#define T_ 2048
#define M_ (B_*T_)          // 8192

#define MD ((size_t)M_*(size_t)D_)   // 16,777,216
#define DD ((size_t)D_*(size_t)D_)   //  4,194,304

#define NCH 32
#define CL  (T_/NCH)                 // 64
#define BDN (B_*NCH*D_)              // 262,144

// ---------------- scratch (static device globals — allocation-free) --------
__device__ __align__(256) __nv_bfloat16 g_xh[3*MD];
__device__ __align__(256) __nv_bfloat16 g_xl[3*MD];
__device__ __align__(256) __nv_bfloat16 g_wh[4*DD];
__device__ __align__(256) __nv_bfloat16 g_wl[4*DD];
__device__ __align__(256) float         g_kvr[3*MD];
__device__ __align__(256) __nv_bfloat16 g_uh[MD];
__device__ __align__(256) __nv_bfloat16 g_ul[MD];
__device__ __align__(256) float         g_agg[3*BDN];   // chunk aggregates
__device__ __align__(256) float         g_car[3*BDN];   // chunk carry-ins

// ---------------- weight hi/lo split ----------------
__global__ void wconv_kernel(const float* __restrict__ W0, const float* __restrict__ W1,
                             const float* __restrict__ W2, const float* __restrict__ W3)
{
    size_t i = (size_t)blockIdx.x * blockDim.x + threadIdx.x;
    if (i >= 4*DD) return;
    size_t which = i / DD;
    const float* Ws = (which == 0) ? W0 : (which == 1) ? W1 : (which == 2) ? W2 : W3;
    float w = Ws[i - which*DD];
    __nv_bfloat16 h = __float2bfloat16(w);
    g_wh[i] = h;
    g_wl[i] = __float2bfloat16(w - __bfloat162float(h));
}

// ---------------- time-shift mix + hi/lo split ----------------
__global__ void mix_kernel(const float* __restrict__ x,
                           const float* __restrict__ mk,
                           const float* __restrict__ mv,
                           const float* __restrict__ mr)
{
    size_t i = (size_t)blockIdx.x * blockDim.x + threadIdx.x;
    if (i >= MD) return;
    int d = (int)(i & (size_t)(D_-1));
    int t = (int)((i / D_) & (size_t)(T_-1));
    float xv = x[i];
    float lx = (t > 0) ? x[i - D_] : 0.0f;
    float dx = xv - lx;

    float a = fmaf(dx, mk[d], lx);
    __nv_bfloat16 h = __float2bfloat16(a);
    g_xh[i]        = h;
    g_xl[i]        = __float2bfloat16(a - __bfloat162float(h));

    a = fmaf(dx, mv[d], lx);
    h = __float2bfloat16(a);
    g_xh[MD + i]   = h;
    g_xl[MD + i]   = __float2bfloat16(a - __bfloat162float(h));

    a = fmaf(dx, mr[d], lx);
    h = __float2bfloat16(a);
    g_xh[2*MD + i] = h;
    g_xl[2*MD + i] = __float2bfloat16(a - __bfloat162float(h));
}

// ---------------- bf16-split GEMM: C[M,N] = A[M,K] * B[N,K]^T ----------------
// C = Ah*Bh + Ah*Bl + Al*Bh  (fp32 accum) — near-fp32 accuracy.
// 3-stage cp.async ring: compute(s) overlaps loads of s+1 AND s+2.
#define BM 128
#define BN 128
#define BK 32
#define NSTG 3
#define STAGE_ELEMS (4*BM*BK)        // 4 operand tiles per stage (bf16 elems)

__device__ __forceinline__ uint32_t cvta_s(const void* p) {
    return (uint32_t)__cvta_generic_to_shared(p);
}
__device__ __forceinline__ void cp16(void* s, const void* g) {
    asm volatile("cp.async.cg.shared.global [%0], [%1], 16;\n"
                 :: "r"(cvta_s(s)), "l"(g));
}
__device__ __forceinline__ int swoff(int r, int c) {
    return r*BK + ((c ^ ((r >> 1) & 3)) << 3);
}

#define MMA_BF16(cc, aa, bb)                                                    \
    asm volatile("mma.sync.aligned.m16n8k16.row.col.f32.bf16.bf16.f32 "          \
                 "{%0,%1,%2,%3},{%4,%5,%6,%7},{%8,%9},{%0,%1,%2,%3};\n"          \
                 : "+f"(cc[0]), "+f"(cc[1]), "+f"(cc[2]), "+f"(cc[3])            \
                 : "r"(aa[0]), "r"(aa[1]), "r"(aa[2]), "r"(aa[3]),               \
                   "r"(bb[0]), "r"(bb[1]))

__global__ void __launch_bounds__(256, 2)   // <=128 regs -> 2 CTAs/SM
gemm_kernel(const __nv_bfloat16* __restrict__ Ah, const __nv_bfloat16* __restrict__ Al,
            const __nv_bfloat16* __restrict__ Bh, const __nv_bfloat16* __restrict__ Bl,
            float* __restrict__ C, int M, int N, int K)
{
    extern __shared__ __align__(16) char smem_raw[];
    __nv_bfloat16* sm = (__nv_bfloat16*)smem_raw;   // [NSTG][4][BM*BK]

    const int tid  = threadIdx.x;
    const int lane = tid & 31;
    const int warp = tid >> 5;
    const int wm   = warp >> 2;   // 0..1  (64 rows each)
    const int wn   = warp & 3;    // 0..3  (32 cols each)

    const int bm = blockIdx.y * BM;
    const int bn = blockIdx.x * BN;

    float c[4][4][4];
    #pragma unroll
    for (int i = 0; i < 4; i++)
        #pragma unroll
        for (int j = 0; j < 4; j++)
            #pragma unroll
            for (int q = 0; q < 4; q++) c[i][j][q] = 0.0f;

    const __nv_bfloat16* gbase[4] = { Ah + (size_t)bm*K, Al + (size_t)bm*K,
                                      Bh + (size_t)bn*K, Bl + (size_t)bn*K };

    auto issue_loads = [&](int s, int bi) {
        int k0 = s * BK;
        __nv_bfloat16* st = sm + bi * STAGE_ELEMS;
        #pragma unroll
        for (int q = 0; q < 8; q++) {
            int cid = tid + q*256;              // 2048 16B-chunks per stage
            int op  = cid >> 9;                 // 0..3
            int wi  = cid & 511;
            int rr  = wi >> 2, cc = wi & 3;
            cp16(st + op*(BM*BK) + swoff(rr, cc),
                 gbase[op] + (size_t)rr*K + k0 + cc*8);
        }
        asm volatile("cp.async.commit_group;\n");
    };

    auto compute_stage = [&](int bi) {
        __nv_bfloat16* sAh = sm + bi*STAGE_ELEMS;
        __nv_bfloat16* sAl = sAh + BM*BK;
        __nv_bfloat16* sBh = sAl + BM*BK;
        __nv_bfloat16* sBl = sBh + BM*BK;
        #pragma unroll
        for (int kk = 0; kk < 2; kk++) {
            uint32_t bhf[4][2], blf[4][2];
            #pragma unroll
            for (int p = 0; p < 2; p++) {
                int rr = wn*32 + p*16 + (lane & 15);
                int cc = kk*2 + (lane >> 4);
                uint32_t r0, r1, r2, r3, ad;
                ad = cvta_s(sBh + swoff(rr, cc));
                asm volatile("ldmatrix.sync.aligned.m8n8.x4.shared.b16 {%0,%1,%2,%3},[%4];\n"
                             : "=r"(r0), "=r"(r1), "=r"(r2), "=r"(r3) : "r"(ad));
                bhf[2*p][0] = r0; bhf[2*p][1] = r2;
                bhf[2*p+1][0] = r1; bhf[2*p+1][1] = r3;
                ad = cvta_s(sBl + swoff(rr, cc));
                asm volatile("ldmatrix.sync.aligned.m8n8.x4.shared.b16 {%0,%1,%2,%3},[%4];\n"
                             : "=r"(r0), "=r"(r1), "=r"(r2), "=r"(r3) : "r"(ad));
                blf[2*p][0] = r0; blf[2*p][1] = r2;
                blf[2*p+1][0] = r1; blf[2*p+1][1] = r3;
            }
            #pragma unroll
            for (int mt = 0; mt < 4; mt++) {
                int rr = wm*64 + mt*16 + (lane & 15);
                int cc = kk*2 + (lane >> 4);
                uint32_t ah[4], al4[4], ad;
                ad = cvta_s(sAh + swoff(rr, cc));
                asm volatile("ldmatrix.sync.aligned.m8n8.x4.shared.b16 {%0,%1,%2,%3},[%4];\n"
                             : "=r"(ah[0]), "=r"(ah[1]), "=r"(ah[2]), "=r"(ah[3]) : "r"(ad));
                ad = cvta_s(sAl + swoff(rr, cc));
                asm volatile("ldmatrix.sync.aligned.m8n8.x4.shared.b16 {%0,%1,%2,%3},[%4];\n"
                             : "=r"(al4[0]), "=r"(al4[1]), "=r"(al4[2]), "=r"(al4[3]) : "r"(ad));
                #pragma unroll
                for (int nt = 0; nt < 4; nt++) {
                    MMA_BF16(c[mt][nt], ah,  bhf[nt]);
                    MMA_BF16(c[mt][nt], ah,  blf[nt]);
                    MMA_BF16(c[mt][nt], al4, bhf[nt]);
                }
            }
        }
    };

    const int NS = K / BK;                     // 64 stages
    issue_loads(0, 0);
    issue_loads(1, 1);

    for (int s = 0; s < NS; s++) {
        const int bi = s % NSTG;
        if (s + 1 < NS) asm volatile("cp.async.wait_group 1;\n" ::: "memory");
        else            asm volatile("cp.async.wait_group 0;\n" ::: "memory");
        __syncthreads();                       // stage-s ready; stage s-1 buffer free
        if (s + 2 < NS) issue_loads(s + 2, (s + 2) % NSTG);
        compute_stage(bi);
    }

    // epilogue
    #pragma unroll
    for (int mt = 0; mt < 4; mt++) {
        #pragma unroll
        for (int nt = 0; nt < 4; nt++) {
            int row = bm + wm*64 + mt*16 + (lane >> 2);
            int col = bn + wn*32 + nt*8 + (lane & 3)*2;
            *reinterpret_cast<float2*>(C + (size_t)row*N + col) =
                make_float2(c[mt][nt][0], c[mt][nt][1]);
            *reinterpret_cast<float2*>(C + (size_t)(row+8)*N + col) =
                make_float2(c[mt][nt][2], c[mt][nt][3]);
        }
    }
}

// ============================================================================
// WKV parallel scan: 3 phases (linear recurrence on unnormalized state).
// ============================================================================

__global__ void wkv_chunk_kernel(const float* __restrict__ kk, const float* __restrict__ vv,
                                 const float* __restrict__ td)
{
    int g  = blockIdx.x * 256 + threadIdx.x;    // 0 .. BDN-1
    int d  = g & (D_-1);
    int ch = (g >> 11) & (NCH-1);
    int b  = g >> 16;
    float w = expf(td[d]);

    float alpha = 0.0f, beta = 0.0f, eps = -1e30f;
    size_t base = ((size_t)b * T_ + (size_t)ch * CL) * D_ + d;

    #pragma unroll 4
    for (int i = 0; i < CL; i++) {
        size_t idx = base + (size_t)i * D_;
        float kt = kk[idx];
        float vt = vv[idx];
        float ww2  = eps - w;
        float tau2 = fmaxf(ww2, kt);
        float e1b  = __expf(ww2 - tau2);
        float e2b  = __expf(kt - tau2);
        alpha = e1b*alpha + e2b*vt;
        beta  = e1b*beta + e2b;
        eps   = tau2;
    }
    size_t o = ((size_t)b * NCH + ch) * D_ + d;
    g_agg[o]         = alpha;
    g_agg[BDN + o]   = beta;
    g_agg[2*BDN + o] = eps;
}

__global__ void wkv_stitch_kernel(const float* __restrict__ td)
{
    int g = blockIdx.x * 256 + threadIdx.x;     // 0 .. B_*D_-1
    int d = g & (D_-1);
    int b = g >> 11;
    float w  = expf(td[d]);
    float dl = -w * (float)CL;                  // log decay across one chunk

    float a = 0.0f, bt = 0.0f, e = -1e30f;
    #pragma unroll 4
    for (int ch = 0; ch < NCH; ch++) {
        size_t o = ((size_t)b * NCH + ch) * D_ + d;
        g_car[o]         = a;
        g_car[BDN + o]   = bt;
        g_car[2*BDN + o] = e;
        float pa = g_agg[o];
        float pb = g_agg[BDN + o];
        float pe = g_agg[2*BDN + o];
        float ein = e + dl;
        float ne  = fmaxf(ein, pe);
        float f1  = __expf(ein - ne);
        float f2  = __expf(pe - ne);
        a  = f1*a  + f2*pa;
        bt = f1*bt + f2*pb;
        e  = ne;
    }
}

__global__ void wkv_apply_kernel(const float* __restrict__ kk, const float* __restrict__ vv,
                                 const float* __restrict__ rr,
                                 const float* __restrict__ td, const float* __restrict__ tf)
{
    int g  = blockIdx.x * 256 + threadIdx.x;
    int d  = g & (D_-1);
    int ch = (g >> 11) & (NCH-1);
    int b  = g >> 16;
    float w = expf(td[d]);
    float u = tf[d];

    size_t o = ((size_t)b * NCH + ch) * D_ + d;
    float alpha = g_car[o];
    float beta  = g_car[BDN + o];
    float eps   = g_car[2*BDN + o];

    size_t base = ((size_t)b * T_ + (size_t)ch * CL) * D_ + d;

    #pragma unroll 4
    for (int i = 0; i < CL; i++) {
        size_t idx = base + (size_t)i * D_;
        float kt = kk[idx];
        float vt = vv[idx];
        float rt = rr[idx];

        float ww  = u + kt;
        float tau = fmaxf(eps, ww);
        float e1  = __expf(eps - tau);
        float e2  = __expf(ww - tau);
        float out = (e1*alpha + e2*vt) / (e1*beta + e2);

        float ww2  = eps - w;
        float tau2 = fmaxf(ww2, kt);
        float e1b  = __expf(ww2 - tau2);
        float e2b  = __expf(kt - tau2);
        alpha = e1b*alpha + e2b*vt;
        beta  = e1b*beta + e2b;
        eps   = tau2;

        float sr = 1.0f / (1.0f + __expf(-rt));
        float uo = out * sr;
        __nv_bfloat16 h = __float2bfloat16(uo);
        g_uh[idx] = h;
        g_ul[idx] = __float2bfloat16(uo - __bfloat162float(h));
    }
}

// ---------------- launch ----------------
extern "C" void kernel_launch(void* const* d_in, const int* in_sizes, int n_in,
                              void* d_out, int out_size)
{
    const float* x  = (const float*)d_in[0];
    const float* td = (const float*)d_in[1];
    const float* tf = (const float*)d_in[2];
    const float* mk = (const float*)d_in[3];
    const float* mv = (const float*)d_in[4];
    const float* mr = (const float*)d_in[5];
    const float* Wk = (const float*)d_in[6];
    const float* Wv = (const float*)d_in[7];
    const float* Wr = (const float*)d_in[8];
    const float* Wo = (const float*)d_in[9];
    float* out = (float*)d_out;

    __nv_bfloat16 *xh, *xl, *wh, *wl, *uh, *ul;
    float* kvr;
    cudaGetSymbolAddress((void**)&xh,  g_xh);
    cudaGetSymbolAddress((void**)&xl,  g_xl);
    cudaGetSymbolAddress((void**)&wh,  g_wh);
    cudaGetSymbolAddress((void**)&wl,  g_wl);
    cudaGetSymbolAddress((void**)&kvr, g_kvr);
    cudaGetSymbolAddress((void**)&uh,  g_uh);
    cudaGetSymbolAddress((void**)&ul,  g_ul);

    const int GEMM_SMEM = NSTG * STAGE_ELEMS * (int)sizeof(__nv_bfloat16);  // 98304
    cudaFuncSetAttribute(gemm_kernel, cudaFuncAttributeMaxDynamicSharedMemorySize, GEMM_SMEM);

    wconv_kernel<<<(unsigned)((4*DD + 255) / 256), 256>>>(Wk, Wv, Wr, Wo);
    mix_kernel<<<(unsigned)((MD + 255) / 256), 256>>>(x, mk, mv, mr);

    dim3 grid(D_ / BN, M_ / BM);   // (16, 64)
    for (int i = 0; i < 3; i++) {
        gemm_kernel<<<grid, 256, GEMM_SMEM>>>(xh + (size_t)i*MD, xl + (size_t)i*MD,
                                              wh + (size_t)i*DD, wl + (size_t)i*DD,
                                              kvr + (size_t)i*MD, M_, D_, D_);
    }

    wkv_chunk_kernel<<<BDN/256, 256>>>(kvr, kvr + MD, td);
    wkv_stitch_kernel<<<(B_*D_)/256, 256>>>(td);
    wkv_apply_kernel<<<BDN/256, 256>>>(kvr, kvr + MD, kvr + 2*MD, td, tf);

    gemm_kernel<<<grid, 256, GEMM_SMEM>>>(uh, ul, wh + 3*DD, wl + 3*DD,
                                          out, M_, D_, D_);
}

// round 6
// speedup vs baseline: 1.0002x; 1.0002x over previous
#include <cuda_runtime.h>
#include <cuda_bf16.h>
#include <cstdint>

// ---------------- problem constants ----------------
#define D_ 2048
#define B_ 4
#define T_ 2048
#define M_ (B_*T_)          // 8192

#define MD ((size_t)M_*(size_t)D_)   // 16,777,216
#define DD ((size_t)D_*(size_t)D_)   //  4,194,304

#define NCH 32
#define CL  (T_/NCH)                 // 64
#define BDN (B_*NCH*D_)              // 262,144

// ---------------- scratch (static device globals — allocation-free) --------
__device__ __align__(256) __nv_bfloat16 g_xh[3*MD];
__device__ __align__(256) __nv_bfloat16 g_xl[3*MD];
__device__ __align__(256) __nv_bfloat16 g_wh[4*DD];
__device__ __align__(256) __nv_bfloat16 g_wl[4*DD];
__device__ __align__(256) float         g_kvr[3*MD];
__device__ __align__(256) __nv_bfloat16 g_uh[MD];
__device__ __align__(256) __nv_bfloat16 g_ul[MD];
__device__ __align__(256) float         g_agg[3*BDN];   // chunk aggregates
__device__ __align__(256) float         g_car[3*BDN];   // chunk carry-ins

// ---------------- weight hi/lo split ----------------
__global__ void wconv_kernel(const float* __restrict__ W0, const float* __restrict__ W1,
                             const float* __restrict__ W2, const float* __restrict__ W3)
{
    size_t i = (size_t)blockIdx.x * blockDim.x + threadIdx.x;
    if (i >= 4*DD) return;
    size_t which = i / DD;
    const float* Ws = (which == 0) ? W0 : (which == 1) ? W1 : (which == 2) ? W2 : W3;
    float w = Ws[i - which*DD];
    __nv_bfloat16 h = __float2bfloat16(w);
    g_wh[i] = h;
    g_wl[i] = __float2bfloat16(w - __bfloat162float(h));
}

// ---------------- time-shift mix + hi/lo split ----------------
__global__ void mix_kernel(const float* __restrict__ x,
                           const float* __restrict__ mk,
                           const float* __restrict__ mv,
                           const float* __restrict__ mr)
{
    size_t i = (size_t)blockIdx.x * blockDim.x + threadIdx.x;
    if (i >= MD) return;
    int d = (int)(i & (size_t)(D_-1));
    int t = (int)((i / D_) & (size_t)(T_-1));
    float xv = x[i];
    float lx = (t > 0) ? x[i - D_] : 0.0f;
    float dx = xv - lx;

    float a = fmaf(dx, mk[d], lx);
    __nv_bfloat16 h = __float2bfloat16(a);
    g_xh[i]        = h;
    g_xl[i]        = __float2bfloat16(a - __bfloat162float(h));

    a = fmaf(dx, mv[d], lx);
    h = __float2bfloat16(a);
    g_xh[MD + i]   = h;
    g_xl[MD + i]   = __float2bfloat16(a - __bfloat162float(h));

    a = fmaf(dx, mr[d], lx);
    h = __float2bfloat16(a);
    g_xh[2*MD + i] = h;
    g_xl[2*MD + i] = __float2bfloat16(a - __bfloat162float(h));
}

// ---------------- bf16-split GEMM: C[M,N] = A[M,K] * B[N,K]^T ----------------
// C = Ah*Bh + Ah*Bl + Al*Bh  (fp32 accum) — near-fp32 accuracy.
// 3-stage cp.async ring; MMA passes interleaved across nt to break
// accumulator RAW chains (per-accumulator FP order unchanged: hh,hl,lh).
#define BM 128
#define BN 128
#define BK 32
#define NSTG 3
#define STAGE_ELEMS (4*BM*BK)        // 4 operand tiles per stage (bf16 elems)

__device__ __forceinline__ uint32_t cvta_s(const void* p) {
    return (uint32_t)__cvta_generic_to_shared(p);
}
__device__ __forceinline__ void cp16(void* s, const void* g) {
    asm volatile("cp.async.cg.shared.global [%0], [%1], 16;\n"
                 :: "r"(cvta_s(s)), "l"(g));
}
__device__ __forceinline__ int swoff(int r, int c) {
    return r*BK + ((c ^ ((r >> 1) & 3)) << 3);
}

#define MMA_BF16(cc, aa, bb)                                                    \
    asm volatile("mma.sync.aligned.m16n8k16.row.col.f32.bf16.bf16.f32 "          \
                 "{%0,%1,%2,%3},{%4,%5,%6,%7},{%8,%9},{%0,%1,%2,%3};\n"          \
                 : "+f"(cc[0]), "+f"(cc[1]), "+f"(cc[2]), "+f"(cc[3])            \
                 : "r"(aa[0]), "r"(aa[1]), "r"(aa[2]), "r"(aa[3]),               \
                   "r"(bb[0]), "r"(bb[1]))

__global__ void __launch_bounds__(256, 2)   // <=128 regs -> 2 CTAs/SM
gemm_kernel(const __nv_bfloat16* __restrict__ Ah, const __nv_bfloat16* __restrict__ Al,
            const __nv_bfloat16* __restrict__ Bh, const __nv_bfloat16* __restrict__ Bl,
            float* __restrict__ C, int M, int N, int K)
{
    extern __shared__ __align__(16) char smem_raw[];
    __nv_bfloat16* sm = (__nv_bfloat16*)smem_raw;   // [NSTG][4][BM*BK]

    const int tid  = threadIdx.x;
    const int lane = tid & 31;
    const int warp = tid >> 5;
    const int wm   = warp >> 2;   // 0..1  (64 rows each)
    const int wn   = warp & 3;    // 0..3  (32 cols each)

    const int bm = blockIdx.y * BM;
    const int bn = blockIdx.x * BN;

    float c[4][4][4];
    #pragma unroll
    for (int i = 0; i < 4; i++)
        #pragma unroll
        for (int j = 0; j < 4; j++)
            #pragma unroll
            for (int q = 0; q < 4; q++) c[i][j][q] = 0.0f;

    const __nv_bfloat16* gbase[4] = { Ah + (size_t)bm*K, Al + (size_t)bm*K,
                                      Bh + (size_t)bn*K, Bl + (size_t)bn*K };

    auto issue_loads = [&](int s, int bi) {
        int k0 = s * BK;
        __nv_bfloat16* st = sm + bi * STAGE_ELEMS;
        #pragma unroll
        for (int q = 0; q < 8; q++) {
            int cid = tid + q*256;              // 2048 16B-chunks per stage
            int op  = cid >> 9;                 // 0..3
            int wi  = cid & 511;
            int rr  = wi >> 2, cc = wi & 3;
            cp16(st + op*(BM*BK) + swoff(rr, cc),
                 gbase[op] + (size_t)rr*K + k0 + cc*8);
        }
        asm volatile("cp.async.commit_group;\n");
    };

    auto compute_stage = [&](int bi) {
        __nv_bfloat16* sAh = sm + bi*STAGE_ELEMS;
        __nv_bfloat16* sAl = sAh + BM*BK;
        __nv_bfloat16* sBh = sAl + BM*BK;
        __nv_bfloat16* sBl = sBh + BM*BK;
        #pragma unroll
        for (int kk = 0; kk < 2; kk++) {
            uint32_t bhf[4][2], blf[4][2];
            #pragma unroll
            for (int p = 0; p < 2; p++) {
                int rr = wn*32 + p*16 + (lane & 15);
                int cc = kk*2 + (lane >> 4);
                uint32_t r0, r1, r2, r3, ad;
                ad = cvta_s(sBh + swoff(rr, cc));
                asm volatile("ldmatrix.sync.aligned.m8n8.x4.shared.b16 {%0,%1,%2,%3},[%4];\n"
                             : "=r"(r0), "=r"(r1), "=r"(r2), "=r"(r3) : "r"(ad));
                bhf[2*p][0] = r0; bhf[2*p][1] = r2;
                bhf[2*p+1][0] = r1; bhf[2*p+1][1] = r3;
                ad = cvta_s(sBl + swoff(rr, cc));
                asm volatile("ldmatrix.sync.aligned.m8n8.x4.shared.b16 {%0,%1,%2,%3},[%4];\n"
                             : "=r"(r0), "=r"(r1), "=r"(r2), "=r"(r3) : "r"(ad));
                blf[2*p][0] = r0; blf[2*p][1] = r2;
                blf[2*p+1][0] = r1; blf[2*p+1][1] = r3;
            }
            #pragma unroll
            for (int mt = 0; mt < 4; mt++) {
                int rr = wm*64 + mt*16 + (lane & 15);
                int cc = kk*2 + (lane >> 4);
                uint32_t ah[4], al4[4], ad;
                ad = cvta_s(sAh + swoff(rr, cc));
                asm volatile("ldmatrix.sync.aligned.m8n8.x4.shared.b16 {%0,%1,%2,%3},[%4];\n"
                             : "=r"(ah[0]), "=r"(ah[1]), "=r"(ah[2]), "=r"(ah[3]) : "r"(ad));
                ad = cvta_s(sAl + swoff(rr, cc));
                asm volatile("ldmatrix.sync.aligned.m8n8.x4.shared.b16 {%0,%1,%2,%3},[%4];\n"
                             : "=r"(al4[0]), "=r"(al4[1]), "=r"(al4[2]), "=r"(al4[3]) : "r"(ad));
                // pass-major order: dependent writes to c[mt][nt] are separated
                // by 4 independent MMAs (no accumulator RAW back-pressure).
                #pragma unroll
                for (int nt = 0; nt < 4; nt++) MMA_BF16(c[mt][nt], ah,  bhf[nt]);
                #pragma unroll
                for (int nt = 0; nt < 4; nt++) MMA_BF16(c[mt][nt], ah,  blf[nt]);
                #pragma unroll
                for (int nt = 0; nt < 4; nt++) MMA_BF16(c[mt][nt], al4, bhf[nt]);
            }
        }
    };

    const int NS = K / BK;                     // 64 stages
    issue_loads(0, 0);
    issue_loads(1, 1);

    for (int s = 0; s < NS; s++) {
        const int bi = s % NSTG;
        if (s + 1 < NS) asm volatile("cp.async.wait_group 1;\n" ::: "memory");
        else            asm volatile("cp.async.wait_group 0;\n" ::: "memory");
        __syncthreads();                       // stage-s ready; stage s-1 buffer free
        if (s + 2 < NS) issue_loads(s + 2, (s + 2) % NSTG);
        compute_stage(bi);
    }

    // epilogue
    #pragma unroll
    for (int mt = 0; mt < 4; mt++) {
        #pragma unroll
        for (int nt = 0; nt < 4; nt++) {
            int row = bm + wm*64 + mt*16 + (lane >> 2);
            int col = bn + wn*32 + nt*8 + (lane & 3)*2;
            *reinterpret_cast<float2*>(C + (size_t)row*N + col) =
                make_float2(c[mt][nt][0], c[mt][nt][1]);
            *reinterpret_cast<float2*>(C + (size_t)(row+8)*N + col) =
                make_float2(c[mt][nt][2], c[mt][nt][3]);
        }
    }
}

// ============================================================================
// WKV parallel scan: 3 phases (linear recurrence on unnormalized state).
// ============================================================================

__global__ void wkv_chunk_kernel(const float* __restrict__ kk, const float* __restrict__ vv,
                                 const float* __restrict__ td)
{
    int g  = blockIdx.x * 256 + threadIdx.x;    // 0 .. BDN-1
    int d  = g & (D_-1);
    int ch = (g >> 11) & (NCH-1);
    int b  = g >> 16;
    float w = expf(td[d]);

    float alpha = 0.0f, beta = 0.0f, eps = -1e30f;
    size_t base = ((size_t)b * T_ + (size_t)ch * CL) * D_ + d;

    #pragma unroll 4
    for (int i = 0; i < CL; i++) {
        size_t idx = base + (size_t)i * D_;
        float kt = kk[idx];
        float vt = vv[idx];
        float ww2  = eps - w;
        float tau2 = fmaxf(ww2, kt);
        float e1b  = __expf(ww2 - tau2);
        float e2b  = __expf(kt - tau2);
        alpha = e1b*alpha + e2b*vt;
        beta  = e1b*beta + e2b;
        eps   = tau2;
    }
    size_t o = ((size_t)b * NCH + ch) * D_ + d;
    g_agg[o]         = alpha;
    g_agg[BDN + o]   = beta;
    g_agg[2*BDN + o] = eps;
}

__global__ void wkv_stitch_kernel(const float* __restrict__ td)
{
    int g = blockIdx.x * 256 + threadIdx.x;     // 0 .. B_*D_-1
    int d = g & (D_-1);
    int b = g >> 11;
    float w  = expf(td[d]);
    float dl = -w * (float)CL;                  // log decay across one chunk

    float a = 0.0f, bt = 0.0f, e = -1e30f;
    #pragma unroll 4
    for (int ch = 0; ch < NCH; ch++) {
        size_t o = ((size_t)b * NCH + ch) * D_ + d;
        g_car[o]         = a;
        g_car[BDN + o]   = bt;
        g_car[2*BDN + o] = e;
        float pa = g_agg[o];
        float pb = g_agg[BDN + o];
        float pe = g_agg[2*BDN + o];
        float ein = e + dl;
        float ne  = fmaxf(ein, pe);
        float f1  = __expf(ein - ne);
        float f2  = __expf(pe - ne);
        a  = f1*a  + f2*pa;
        bt = f1*bt + f2*pb;
        e  = ne;
    }
}

__global__ void wkv_apply_kernel(const float* __restrict__ kk, const float* __restrict__ vv,
                                 const float* __restrict__ rr,
                                 const float* __restrict__ td, const float* __restrict__ tf)
{
    int g  = blockIdx.x * 256 + threadIdx.x;
    int d  = g & (D_-1);
    int ch = (g >> 11) & (NCH-1);
    int b  = g >> 16;
    float w = expf(td[d]);
    float u = tf[d];

    size_t o = ((size_t)b * NCH + ch) * D_ + d;
    float alpha = g_car[o];
    float beta  = g_car[BDN + o];
    float eps   = g_car[2*BDN + o];

    size_t base = ((size_t)b * T_ + (size_t)ch * CL) * D_ + d;

    #pragma unroll 4
    for (int i = 0; i < CL; i++) {
        size_t idx = base + (size_t)i * D_;
        float kt = kk[idx];
        float vt = vv[idx];
        float rt = rr[idx];

        float ww  = u + kt;
        float tau = fmaxf(eps, ww);
        float e1  = __expf(eps - tau);
        float e2  = __expf(ww - tau);
        float out = (e1*alpha + e2*vt) / (e1*beta + e2);

        float ww2  = eps - w;
        float tau2 = fmaxf(ww2, kt);
        float e1b  = __expf(ww2 - tau2);
        float e2b  = __expf(kt - tau2);
        alpha = e1b*alpha + e2b*vt;
        beta  = e1b*beta + e2b;
        eps   = tau2;

        float sr = 1.0f / (1.0f + __expf(-rt));
        float uo = out * sr;
        __nv_bfloat16 h = __float2bfloat16(uo);
        g_uh[idx] = h;
        g_ul[idx] = __float2bfloat16(uo - __bfloat162float(h));
    }
}

// ---------------- launch ----------------
extern "C" void kernel_launch(void* const* d_in, const int* in_sizes, int n_in,
                              void* d_out, int out_size)
{
    const float* x  = (const float*)d_in[0];
    const float* td = (const float*)d_in[1];
    const float* tf = (const float*)d_in[2];
    const float* mk = (const float*)d_in[3];
    const float* mv = (const float*)d_in[4];
    const float* mr = (const float*)d_in[5];
    const float* Wk = (const float*)d_in[6];
    const float* Wv = (const float*)d_in[7];
    const float* Wr = (const float*)d_in[8];
    const float* Wo = (const float*)d_in[9];
    float* out = (float*)d_out;

    __nv_bfloat16 *xh, *xl, *wh, *wl, *uh, *ul;
    float* kvr;
    cudaGetSymbolAddress((void**)&xh,  g_xh);
    cudaGetSymbolAddress((void**)&xl,  g_xl);
    cudaGetSymbolAddress((void**)&wh,  g_wh);
    cudaGetSymbolAddress((void**)&wl,  g_wl);
    cudaGetSymbolAddress((void**)&kvr, g_kvr);
    cudaGetSymbolAddress((void**)&uh,  g_uh);
    cudaGetSymbolAddress((void**)&ul,  g_ul);

    const int GEMM_SMEM = NSTG * STAGE_ELEMS * (int)sizeof(__nv_bfloat16);  // 98304
    cudaFuncSetAttribute(gemm_kernel, cudaFuncAttributeMaxDynamicSharedMemorySize, GEMM_SMEM);

    wconv_kernel<<<(unsigned)((4*DD + 255) / 256), 256>>>(Wk, Wv, Wr, Wo);
    mix_kernel<<<(unsigned)((MD + 255) / 256), 256>>>(x, mk, mv, mr);

    dim3 grid(D_ / BN, M_ / BM);   // (16, 64)
    for (int i = 0; i < 3; i++) {
        gemm_kernel<<<grid, 256, GEMM_SMEM>>>(xh + (size_t)i*MD, xl + (size_t)i*MD,
                                              wh + (size_t)i*DD, wl + (size_t)i*DD,
                                              kvr + (size_t)i*MD, M_, D_, D_);
    }

    wkv_chunk_kernel<<<BDN/256, 256>>>(kvr, kvr + MD, td);
    wkv_stitch_kernel<<<(B_*D_)/256, 256>>>(td);
    wkv_apply_kernel<<<BDN/256, 256>>>(kvr, kvr + MD, kvr + 2*MD, td, tf);

    gemm_kernel<<<grid, 256, GEMM_SMEM>>>(uh, ul, wh + 3*DD, wl + 3*DD,
                                          out, M_, D_, D_);
}

// round 7
// speedup vs baseline: 1.5468x; 1.5464x over previous
#include <cuda_runtime.h>
#include <cuda_fp16.h>
#include <cstdint>

// ---------------- problem constants ----------------
#define D_ 2048
#define B_ 4
#define T_ 2048
#define M_ (B_*T_)          // 8192

#define MD ((size_t)M_*(size_t)D_)   // 16,777,216
#define DD ((size_t)D_*(size_t)D_)   //  4,194,304

#define NCH 32
#define CL  (T_/NCH)                 // 64
#define BDN (B_*NCH*D_)              // 262,144

// ---------------- scratch (static device globals — allocation-free) --------
__device__ __align__(256) __half g_xh[3*MD];    // mixed activations (fp16, hi only)
__device__ __align__(256) __half g_wh[4*DD];    // weights hi (fp16)
__device__ __align__(256) __half g_wl[4*DD];    // weights lo (fp16, subnormal ok)
__device__ __align__(256) float  g_kvr[3*MD];   // k, v, r (fp32 GEMM outputs)
__device__ __align__(256) __half g_uh[MD];      // wkv*sigmoid(r) (fp16)
__device__ __align__(256) float  g_agg[3*BDN];  // chunk aggregates
__device__ __align__(256) float  g_car[3*BDN];  // chunk carry-ins

// ---------------- weight hi/lo split (fp16) ----------------
__global__ void wconv_kernel(const float* __restrict__ W0, const float* __restrict__ W1,
                             const float* __restrict__ W2, const float* __restrict__ W3)
{
    size_t i = (size_t)blockIdx.x * blockDim.x + threadIdx.x;
    if (i >= 4*DD) return;
    size_t which = i / DD;
    const float* Ws = (which == 0) ? W0 : (which == 1) ? W1 : (which == 2) ? W2 : W3;
    float w = Ws[i - which*DD];
    __half h = __float2half(w);
    g_wh[i] = h;
    g_wl[i] = __float2half(w - __half2float(h));
}

// ---------------- time-shift mix -> fp16 ----------------
__global__ void mix_kernel(const float* __restrict__ x,
                           const float* __restrict__ mk,
                           const float* __restrict__ mv,
                           const float* __restrict__ mr)
{
    size_t i = (size_t)blockIdx.x * blockDim.x + threadIdx.x;
    if (i >= MD) return;
    int d = (int)(i & (size_t)(D_-1));
    int t = (int)((i / D_) & (size_t)(T_-1));
    float xv = x[i];
    float lx = (t > 0) ? x[i - D_] : 0.0f;
    float dx = xv - lx;

    g_xh[i]        = __float2half(fmaf(dx, mk[d], lx));
    g_xh[MD + i]   = __float2half(fmaf(dx, mv[d], lx));
    g_xh[2*MD + i] = __float2half(fmaf(dx, mr[d], lx));
}

// ---------------- fp16 2-pass GEMM: C[M,N] = A[M,K] * B[N,K]^T ---------------
// C = A*Bh + A*Bl  (fp32 accum); dropped term A_lo*B ~ 2^-12 rms.
#define BM 128
#define BN 128
#define BK 32
#define NSTG 3
#define STAGE_ELEMS (3*BM*BK)        // 3 operand tiles per stage (fp16 elems)

__device__ __forceinline__ uint32_t cvta_s(const void* p) {
    return (uint32_t)__cvta_generic_to_shared(p);
}
__device__ __forceinline__ void cp16(void* s, const void* g) {
    asm volatile("cp.async.cg.shared.global [%0], [%1], 16;\n"
                 :: "r"(cvta_s(s)), "l"(g));
}
__device__ __forceinline__ int swoff(int r, int c) {
    return r*BK + ((c ^ ((r >> 1) & 3)) << 3);
}

#define MMA_FP16(cc, aa, bb)                                                    \
    asm volatile("mma.sync.aligned.m16n8k16.row.col.f32.f16.f16.f32 "            \
                 "{%0,%1,%2,%3},{%4,%5,%6,%7},{%8,%9},{%0,%1,%2,%3};\n"          \
                 : "+f"(cc[0]), "+f"(cc[1]), "+f"(cc[2]), "+f"(cc[3])            \
                 : "r"(aa[0]), "r"(aa[1]), "r"(aa[2]), "r"(aa[3]),               \
                   "r"(bb[0]), "r"(bb[1]))

__global__ void __launch_bounds__(256, 2)   // <=128 regs -> 2 CTAs/SM
gemm_kernel(const __half* __restrict__ Ah,
            const __half* __restrict__ Bh, const __half* __restrict__ Bl,
            float* __restrict__ C, int M, int N, int K)
{
    extern __shared__ __align__(16) char smem_raw[];
    __half* sm = (__half*)smem_raw;   // [NSTG][3][BM*BK]

    const int tid  = threadIdx.x;
    const int lane = tid & 31;
    const int warp = tid >> 5;
    const int wm   = warp >> 2;   // 0..1  (64 rows each)
    const int wn   = warp & 3;    // 0..3  (32 cols each)

    const int bm = blockIdx.y * BM;
    const int bn = blockIdx.x * BN;

    float c[4][4][4];
    #pragma unroll
    for (int i = 0; i < 4; i++)
        #pragma unroll
        for (int j = 0; j < 4; j++)
            #pragma unroll
            for (int q = 0; q < 4; q++) c[i][j][q] = 0.0f;

    const __half* gbase[3] = { Ah + (size_t)bm*K, Bh + (size_t)bn*K, Bl + (size_t)bn*K };

    auto issue_loads = [&](int s, int bi) {
        int k0 = s * BK;
        __half* st = sm + bi * STAGE_ELEMS;
        #pragma unroll
        for (int q = 0; q < 6; q++) {
            int cid = tid + q*256;              // 1536 16B-chunks per stage
            int op  = cid >> 9;                 // 0..2
            int wi  = cid & 511;
            int rr  = wi >> 2, cc = wi & 3;
            cp16(st + op*(BM*BK) + swoff(rr, cc),
                 gbase[op] + (size_t)rr*K + k0 + cc*8);
        }
        asm volatile("cp.async.commit_group;\n");
    };

    auto compute_stage = [&](int bi) {
        __half* sA  = sm + bi*STAGE_ELEMS;
        __half* sBh = sA  + BM*BK;
        __half* sBl = sBh + BM*BK;
        #pragma unroll
        for (int kk = 0; kk < 2; kk++) {
            uint32_t bhf[4][2], blf[4][2];
            #pragma unroll
            for (int p = 0; p < 2; p++) {
                int rr = wn*32 + p*16 + (lane & 15);
                int cc = kk*2 + (lane >> 4);
                uint32_t r0, r1, r2, r3, ad;
                ad = cvta_s(sBh + swoff(rr, cc));
                asm volatile("ldmatrix.sync.aligned.m8n8.x4.shared.b16 {%0,%1,%2,%3},[%4];\n"
                             : "=r"(r0), "=r"(r1), "=r"(r2), "=r"(r3) : "r"(ad));
                bhf[2*p][0] = r0; bhf[2*p][1] = r2;
                bhf[2*p+1][0] = r1; bhf[2*p+1][1] = r3;
                ad = cvta_s(sBl + swoff(rr, cc));
                asm volatile("ldmatrix.sync.aligned.m8n8.x4.shared.b16 {%0,%1,%2,%3},[%4];\n"
                             : "=r"(r0), "=r"(r1), "=r"(r2), "=r"(r3) : "r"(ad));
                blf[2*p][0] = r0; blf[2*p][1] = r2;
                blf[2*p+1][0] = r1; blf[2*p+1][1] = r3;
            }
            #pragma unroll
            for (int mt = 0; mt < 4; mt++) {
                int rr = wm*64 + mt*16 + (lane & 15);
                int cc = kk*2 + (lane >> 4);
                uint32_t ah[4], ad;
                ad = cvta_s(sA + swoff(rr, cc));
                asm volatile("ldmatrix.sync.aligned.m8n8.x4.shared.b16 {%0,%1,%2,%3},[%4];\n"
                             : "=r"(ah[0]), "=r"(ah[1]), "=r"(ah[2]), "=r"(ah[3]) : "r"(ad));
                #pragma unroll
                for (int nt = 0; nt < 4; nt++) MMA_FP16(c[mt][nt], ah, bhf[nt]);
                #pragma unroll
                for (int nt = 0; nt < 4; nt++) MMA_FP16(c[mt][nt], ah, blf[nt]);
            }
        }
    };

    const int NS = K / BK;                     // 64 stages
    issue_loads(0, 0);
    issue_loads(1, 1);

    for (int s = 0; s < NS; s++) {
        const int bi = s % NSTG;
        if (s + 1 < NS) asm volatile("cp.async.wait_group 1;\n" ::: "memory");
        else            asm volatile("cp.async.wait_group 0;\n" ::: "memory");
        __syncthreads();
        if (s + 2 < NS) issue_loads(s + 2, (s + 2) % NSTG);
        compute_stage(bi);
    }

    // epilogue
    #pragma unroll
    for (int mt = 0; mt < 4; mt++) {
        #pragma unroll
        for (int nt = 0; nt < 4; nt++) {
            int row = bm + wm*64 + mt*16 + (lane >> 2);
            int col = bn + wn*32 + nt*8 + (lane & 3)*2;
            *reinterpret_cast<float2*>(C + (size_t)row*N + col) =
                make_float2(c[mt][nt][0], c[mt][nt][1]);
            *reinterpret_cast<float2*>(C + (size_t)(row+8)*N + col) =
                make_float2(c[mt][nt][2], c[mt][nt][3]);
        }
    }
}

// ============================================================================
// WKV parallel scan: 3 phases (linear recurrence on unnormalized state).
// ============================================================================

__global__ void wkv_chunk_kernel(const float* __restrict__ kk, const float* __restrict__ vv,
                                 const float* __restrict__ td)
{
    int g  = blockIdx.x * 256 + threadIdx.x;    // 0 .. BDN-1
    int d  = g & (D_-1);
    int ch = (g >> 11) & (NCH-1);
    int b  = g >> 16;
    float w = expf(td[d]);

    float alpha = 0.0f, beta = 0.0f, eps = -1e30f;
    size_t base = ((size_t)b * T_ + (size_t)ch * CL) * D_ + d;

    #pragma unroll 4
    for (int i = 0; i < CL; i++) {
        size_t idx = base + (size_t)i * D_;
        float kt = kk[idx];
        float vt = vv[idx];
        float ww2  = eps - w;
        float tau2 = fmaxf(ww2, kt);
        float e1b  = __expf(ww2 - tau2);
        float e2b  = __expf(kt - tau2);
        alpha = e1b*alpha + e2b*vt;
        beta  = e1b*beta + e2b;
        eps   = tau2;
    }
    size_t o = ((size_t)b * NCH + ch) * D_ + d;
    g_agg[o]         = alpha;
    g_agg[BDN + o]   = beta;
    g_agg[2*BDN + o] = eps;
}

__global__ void wkv_stitch_kernel(const float* __restrict__ td)
{
    int g = blockIdx.x * 256 + threadIdx.x;     // 0 .. B_*D_-1
    int d = g & (D_-1);
    int b = g >> 11;
    float w  = expf(td[d]);
    float dl = -w * (float)CL;                  // log decay across one chunk

    float a = 0.0f, bt = 0.0f, e = -1e30f;
    #pragma unroll 4
    for (int ch = 0; ch < NCH; ch++) {
        size_t o = ((size_t)b * NCH + ch) * D_ + d;
        g_car[o]         = a;
        g_car[BDN + o]   = bt;
        g_car[2*BDN + o] = e;
        float pa = g_agg[o];
        float pb = g_agg[BDN + o];
        float pe = g_agg[2*BDN + o];
        float ein = e + dl;
        float ne  = fmaxf(ein, pe);
        float f1  = __expf(ein - ne);
        float f2  = __expf(pe - ne);
        a  = f1*a  + f2*pa;
        bt = f1*bt + f2*pb;
        e  = ne;
    }
}

__global__ void wkv_apply_kernel(const float* __restrict__ kk, const float* __restrict__ vv,
                                 const float* __restrict__ rr,
                                 const float* __restrict__ td, const float* __restrict__ tf)
{
    int g  = blockIdx.x * 256 + threadIdx.x;
    int d  = g & (D_-1);
    int ch = (g >> 11) & (NCH-1);
    int b  = g >> 16;
    float w = expf(td[d]);
    float u = tf[d];

    size_t o = ((size_t)b * NCH + ch) * D_ + d;
    float alpha = g_car[o];
    float beta  = g_car[BDN + o];
    float eps   = g_car[2*BDN + o];

    size_t base = ((size_t)b * T_ + (size_t)ch * CL) * D_ + d;

    #pragma unroll 4
    for (int i = 0; i < CL; i++) {
        size_t idx = base + (size_t)i * D_;
        float kt = kk[idx];
        float vt = vv[idx];
        float rt = rr[idx];

        float ww  = u + kt;
        float tau = fmaxf(eps, ww);
        float e1  = __expf(eps - tau);
        float e2  = __expf(ww - tau);
        float out = (e1*alpha + e2*vt) / (e1*beta + e2);

        float ww2  = eps - w;
        float tau2 = fmaxf(ww2, kt);
        float e1b  = __expf(ww2 - tau2);
        float e2b  = __expf(kt - tau2);
        alpha = e1b*alpha + e2b*vt;
        beta  = e1b*beta + e2b;
        eps   = tau2;

        float sr = 1.0f / (1.0f + __expf(-rt));
        g_uh[idx] = __float2half(out * sr);
    }
}

// ---------------- launch ----------------
extern "C" void kernel_launch(void* const* d_in, const int* in_sizes, int n_in,
                              void* d_out, int out_size)
{
    const float* x  = (const float*)d_in[0];
    const float* td = (const float*)d_in[1];
    const float* tf = (const float*)d_in[2];
    const float* mk = (const float*)d_in[3];
    const float* mv = (const float*)d_in[4];
    const float* mr = (const float*)d_in[5];
    const float* Wk = (const float*)d_in[6];
    const float* Wv = (const float*)d_in[7];
    const float* Wr = (const float*)d_in[8];
    const float* Wo = (const float*)d_in[9];
    float* out = (float*)d_out;

    __half *xh, *wh, *wl, *uh;
    float* kvr;
    cudaGetSymbolAddress((void**)&xh,  g_xh);
    cudaGetSymbolAddress((void**)&wh,  g_wh);
    cudaGetSymbolAddress((void**)&wl,  g_wl);
    cudaGetSymbolAddress((void**)&kvr, g_kvr);
    cudaGetSymbolAddress((void**)&uh,  g_uh);

    const int GEMM_SMEM = NSTG * STAGE_ELEMS * (int)sizeof(__half);  // 73728
    cudaFuncSetAttribute(gemm_kernel, cudaFuncAttributeMaxDynamicSharedMemorySize, GEMM_SMEM);

    wconv_kernel<<<(unsigned)((4*DD + 255) / 256), 256>>>(Wk, Wv, Wr, Wo);
    mix_kernel<<<(unsigned)((MD + 255) / 256), 256>>>(x, mk, mv, mr);

    dim3 grid(D_ / BN, M_ / BM);   // (16, 64)
    for (int i = 0; i < 3; i++) {
        gemm_kernel<<<grid, 256, GEMM_SMEM>>>(xh + (size_t)i*MD,
                                              wh + (size_t)i*DD, wl + (size_t)i*DD,
                                              kvr + (size_t)i*MD, M_, D_, D_);
    }

    wkv_chunk_kernel<<<BDN/256, 256>>>(kvr, kvr + MD, td);
    wkv_stitch_kernel<<<(B_*D_)/256, 256>>>(td);
    wkv_apply_kernel<<<BDN/256, 256>>>(kvr, kvr + MD, kvr + 2*MD, td, tf);

    gemm_kernel<<<grid, 256, GEMM_SMEM>>>(uh, wh + 3*DD, wl + 3*DD,
                                          out, M_, D_, D_);
}

// round 8
// speedup vs baseline: 2.3861x; 1.5426x over previous
#include <cuda_runtime.h>
#include <cuda_fp16.h>
#include <cstdint>

// ---------------- problem constants ----------------
#define D_ 2048
#define B_ 4
#define T_ 2048
#define M_ (B_*T_)          // 8192

#define MD ((size_t)M_*(size_t)D_)   // 16,777,216
#define DD ((size_t)D_*(size_t)D_)   //  4,194,304

#define NCH 32
#define CL  (T_/NCH)                 // 64
#define BDN (B_*NCH*D_)              // 262,144

// ---------------- scratch (static device globals — allocation-free) --------
__device__ __align__(256) __half g_xh[3*MD];    // mixed activations (fp16)
__device__ __align__(256) __half g_wh[4*DD];    // weights (fp16)
__device__ __align__(256) float  g_kvr[3*MD];   // k, v, r (fp32 GEMM outputs)
__device__ __align__(256) __half g_uh[MD];      // wkv*sigmoid(r) (fp16)
__device__ __align__(256) float  g_agg[3*BDN];  // chunk aggregates
__device__ __align__(256) float  g_car[3*BDN];  // chunk carry-ins

// ---------------- weight -> fp16 ----------------
__global__ void wconv_kernel(const float* __restrict__ W0, const float* __restrict__ W1,
                             const float* __restrict__ W2, const float* __restrict__ W3)
{
    size_t i = (size_t)blockIdx.x * blockDim.x + threadIdx.x;
    if (i >= 4*DD) return;
    size_t which = i / DD;
    const float* Ws = (which == 0) ? W0 : (which == 1) ? W1 : (which == 2) ? W2 : W3;
    g_wh[i] = __float2half(Ws[i - which*DD]);
}

// ---------------- time-shift mix -> fp16 ----------------
__global__ void mix_kernel(const float* __restrict__ x,
                           const float* __restrict__ mk,
                           const float* __restrict__ mv,
                           const float* __restrict__ mr)
{
    size_t i = (size_t)blockIdx.x * blockDim.x + threadIdx.x;
    if (i >= MD) return;
    int d = (int)(i & (size_t)(D_-1));
    int t = (int)((i / D_) & (size_t)(T_-1));
    float xv = x[i];
    float lx = (t > 0) ? x[i - D_] : 0.0f;
    float dx = xv - lx;

    g_xh[i]        = __float2half(fmaf(dx, mk[d], lx));
    g_xh[MD + i]   = __float2half(fmaf(dx, mv[d], lx));
    g_xh[2*MD + i] = __float2half(fmaf(dx, mr[d], lx));
}

// ---------------- fp16 single-pass GEMM: C[M,N] = A[M,K] * B[N,K]^T ----------
#define BM 128
#define BN 128
#define BK 32
#define NSTG 3
#define STAGE_ELEMS (2*BM*BK)        // 2 operand tiles per stage (fp16 elems)

__device__ __forceinline__ uint32_t cvta_s(const void* p) {
    return (uint32_t)__cvta_generic_to_shared(p);
}
__device__ __forceinline__ void cp16(void* s, const void* g) {
    asm volatile("cp.async.cg.shared.global [%0], [%1], 16;\n"
                 :: "r"(cvta_s(s)), "l"(g));
}
__device__ __forceinline__ int swoff(int r, int c) {
    return r*BK + ((c ^ ((r >> 1) & 3)) << 3);
}

#define MMA_FP16(cc, aa, bb)                                                    \
    asm volatile("mma.sync.aligned.m16n8k16.row.col.f32.f16.f16.f32 "            \
                 "{%0,%1,%2,%3},{%4,%5,%6,%7},{%8,%9},{%0,%1,%2,%3};\n"          \
                 : "+f"(cc[0]), "+f"(cc[1]), "+f"(cc[2]), "+f"(cc[3])            \
                 : "r"(aa[0]), "r"(aa[1]), "r"(aa[2]), "r"(aa[3]),               \
                   "r"(bb[0]), "r"(bb[1]))

__global__ void __launch_bounds__(256, 2)   // <=128 regs -> 2 CTAs/SM
gemm_kernel(const __half* __restrict__ Ah, const __half* __restrict__ Bh,
            float* __restrict__ C, int M, int N, int K)
{
    extern __shared__ __align__(16) char smem_raw[];
    __half* sm = (__half*)smem_raw;   // [NSTG][2][BM*BK]

    const int tid  = threadIdx.x;
    const int lane = tid & 31;
    const int warp = tid >> 5;
    const int wm   = warp >> 2;   // 0..1  (64 rows each)
    const int wn   = warp & 3;    // 0..3  (32 cols each)

    const int bm = blockIdx.y * BM;
    const int bn = blockIdx.x * BN;

    float c[4][4][4];
    #pragma unroll
    for (int i = 0; i < 4; i++)
        #pragma unroll
        for (int j = 0; j < 4; j++)
            #pragma unroll
            for (int q = 0; q < 4; q++) c[i][j][q] = 0.0f;

    const __half* gbase[2] = { Ah + (size_t)bm*K, Bh + (size_t)bn*K };

    auto issue_loads = [&](int s, int bi) {
        int k0 = s * BK;
        __half* st = sm + bi * STAGE_ELEMS;
        #pragma unroll
        for (int q = 0; q < 4; q++) {
            int cid = tid + q*256;              // 1024 16B-chunks per stage
            int op  = cid >> 9;                 // 0..1
            int wi  = cid & 511;
            int rr  = wi >> 2, cc = wi & 3;
            cp16(st + op*(BM*BK) + swoff(rr, cc),
                 gbase[op] + (size_t)rr*K + k0 + cc*8);
        }
        asm volatile("cp.async.commit_group;\n");
    };

    auto compute_stage = [&](int bi) {
        __half* sA = sm + bi*STAGE_ELEMS;
        __half* sB = sA + BM*BK;
        #pragma unroll
        for (int kk = 0; kk < 2; kk++) {
            uint32_t bhf[4][2];
            #pragma unroll
            for (int p = 0; p < 2; p++) {
                int rr = wn*32 + p*16 + (lane & 15);
                int cc = kk*2 + (lane >> 4);
                uint32_t r0, r1, r2, r3, ad;
                ad = cvta_s(sB + swoff(rr, cc));
                asm volatile("ldmatrix.sync.aligned.m8n8.x4.shared.b16 {%0,%1,%2,%3},[%4];\n"
                             : "=r"(r0), "=r"(r1), "=r"(r2), "=r"(r3) : "r"(ad));
                bhf[2*p][0] = r0; bhf[2*p][1] = r2;
                bhf[2*p+1][0] = r1; bhf[2*p+1][1] = r3;
            }
            #pragma unroll
            for (int mt = 0; mt < 4; mt++) {
                int rr = wm*64 + mt*16 + (lane & 15);
                int cc = kk*2 + (lane >> 4);
                uint32_t ah[4], ad;
                ad = cvta_s(sA + swoff(rr, cc));
                asm volatile("ldmatrix.sync.aligned.m8n8.x4.shared.b16 {%0,%1,%2,%3},[%4];\n"
                             : "=r"(ah[0]), "=r"(ah[1]), "=r"(ah[2]), "=r"(ah[3]) : "r"(ad));
                #pragma unroll
                for (int nt = 0; nt < 4; nt++) MMA_FP16(c[mt][nt], ah, bhf[nt]);
            }
        }
    };

    const int NS = K / BK;                     // 64 stages
    issue_loads(0, 0);
    issue_loads(1, 1);

    for (int s = 0; s < NS; s++) {
        const int bi = s % NSTG;
        if (s + 1 < NS) asm volatile("cp.async.wait_group 1;\n" ::: "memory");
        else            asm volatile("cp.async.wait_group 0;\n" ::: "memory");
        __syncthreads();
        if (s + 2 < NS) issue_loads(s + 2, (s + 2) % NSTG);
        compute_stage(bi);
    }

    // epilogue
    #pragma unroll
    for (int mt = 0; mt < 4; mt++) {
        #pragma unroll
        for (int nt = 0; nt < 4; nt++) {
            int row = bm + wm*64 + mt*16 + (lane >> 2);
            int col = bn + wn*32 + nt*8 + (lane & 3)*2;
            *reinterpret_cast<float2*>(C + (size_t)row*N + col) =
                make_float2(c[mt][nt][0], c[mt][nt][1]);
            *reinterpret_cast<float2*>(C + (size_t)(row+8)*N + col) =
                make_float2(c[mt][nt][2], c[mt][nt][3]);
        }
    }
}

// ============================================================================
// WKV parallel scan: 3 phases (linear recurrence on unnormalized state).
// ============================================================================

__global__ void wkv_chunk_kernel(const float* __restrict__ kk, const float* __restrict__ vv,
                                 const float* __restrict__ td)
{
    int g  = blockIdx.x * 256 + threadIdx.x;    // 0 .. BDN-1
    int d  = g & (D_-1);
    int ch = (g >> 11) & (NCH-1);
    int b  = g >> 16;
    float w = expf(td[d]);

    float alpha = 0.0f, beta = 0.0f, eps = -1e30f;
    size_t base = ((size_t)b * T_ + (size_t)ch * CL) * D_ + d;

    #pragma unroll 4
    for (int i = 0; i < CL; i++) {
        size_t idx = base + (size_t)i * D_;
        float kt = kk[idx];
        float vt = vv[idx];
        float ww2  = eps - w;
        float tau2 = fmaxf(ww2, kt);
        float e1b  = __expf(ww2 - tau2);
        float e2b  = __expf(kt - tau2);
        alpha = e1b*alpha + e2b*vt;
        beta  = e1b*beta + e2b;
        eps   = tau2;
    }
    size_t o = ((size_t)b * NCH + ch) * D_ + d;
    g_agg[o]         = alpha;
    g_agg[BDN + o]   = beta;
    g_agg[2*BDN + o] = eps;
}

__global__ void wkv_stitch_kernel(const float* __restrict__ td)
{
    int g = blockIdx.x * 256 + threadIdx.x;     // 0 .. B_*D_-1
    int d = g & (D_-1);
    int b = g >> 11;
    float w  = expf(td[d]);
    float dl = -w * (float)CL;                  // log decay across one chunk

    float a = 0.0f, bt = 0.0f, e = -1e30f;
    #pragma unroll 4
    for (int ch = 0; ch < NCH; ch++) {
        size_t o = ((size_t)b * NCH + ch) * D_ + d;
        g_car[o]         = a;
        g_car[BDN + o]   = bt;
        g_car[2*BDN + o] = e;
        float pa = g_agg[o];
        float pb = g_agg[BDN + o];
        float pe = g_agg[2*BDN + o];
        float ein = e + dl;
        float ne  = fmaxf(ein, pe);
        float f1  = __expf(ein - ne);
        float f2  = __expf(pe - ne);
        a  = f1*a  + f2*pa;
        bt = f1*bt + f2*pb;
        e  = ne;
    }
}

__global__ void wkv_apply_kernel(const float* __restrict__ kk, const float* __restrict__ vv,
                                 const float* __restrict__ rr,
                                 const float* __restrict__ td, const float* __restrict__ tf)
{
    int g  = blockIdx.x * 256 + threadIdx.x;
    int d  = g & (D_-1);
    int ch = (g >> 11) & (NCH-1);
    int b  = g >> 16;
    float w = expf(td[d]);
    float u = tf[d];

    size_t o = ((size_t)b * NCH + ch) * D_ + d;
    float alpha = g_car[o];
    float beta  = g_car[BDN + o];
    float eps   = g_car[2*BDN + o];

    size_t base = ((size_t)b * T_ + (size_t)ch * CL) * D_ + d;

    #pragma unroll 4
    for (int i = 0; i < CL; i++) {
        size_t idx = base + (size_t)i * D_;
        float kt = kk[idx];
        float vt = vv[idx];
        float rt = rr[idx];

        float ww  = u + kt;
        float tau = fmaxf(eps, ww);
        float e1  = __expf(eps - tau);
        float e2  = __expf(ww - tau);
        float out = (e1*alpha + e2*vt) / (e1*beta + e2);

        float ww2  = eps - w;
        float tau2 = fmaxf(ww2, kt);
        float e1b  = __expf(ww2 - tau2);
        float e2b  = __expf(kt - tau2);
        alpha = e1b*alpha + e2b*vt;
        beta  = e1b*beta + e2b;
        eps   = tau2;

        float sr = 1.0f / (1.0f + __expf(-rt));
        g_uh[idx] = __float2half(out * sr);
    }
}

// ---------------- launch ----------------
extern "C" void kernel_launch(void* const* d_in, const int* in_sizes, int n_in,
                              void* d_out, int out_size)
{
    const float* x  = (const float*)d_in[0];
    const float* td = (const float*)d_in[1];
    const float* tf = (const float*)d_in[2];
    const float* mk = (const float*)d_in[3];
    const float* mv = (const float*)d_in[4];
    const float* mr = (const float*)d_in[5];
    const float* Wk = (const float*)d_in[6];
    const float* Wv = (const float*)d_in[7];
    const float* Wr = (const float*)d_in[8];
    const float* Wo = (const float*)d_in[9];
    float* out = (float*)d_out;

    __half *xh, *wh, *uh;
    float* kvr;
    cudaGetSymbolAddress((void**)&xh,  g_xh);
    cudaGetSymbolAddress((void**)&wh,  g_wh);
    cudaGetSymbolAddress((void**)&kvr, g_kvr);
    cudaGetSymbolAddress((void**)&uh,  g_uh);

    const int GEMM_SMEM = NSTG * STAGE_ELEMS * (int)sizeof(__half);  // 49152
    cudaFuncSetAttribute(gemm_kernel, cudaFuncAttributeMaxDynamicSharedMemorySize, GEMM_SMEM);

    wconv_kernel<<<(unsigned)((4*DD + 255) / 256), 256>>>(Wk, Wv, Wr, Wo);
    mix_kernel<<<(unsigned)((MD + 255) / 256), 256>>>(x, mk, mv, mr);

    dim3 grid(D_ / BN, M_ / BM);   // (16, 64)
    for (int i = 0; i < 3; i++) {
        gemm_kernel<<<grid, 256, GEMM_SMEM>>>(xh + (size_t)i*MD,
                                              wh + (size_t)i*DD,
                                              kvr + (size_t)i*MD, M_, D_, D_);
    }

    wkv_chunk_kernel<<<BDN/256, 256>>>(kvr, kvr + MD, td);
    wkv_stitch_kernel<<<(B_*D_)/256, 256>>>(td);
    wkv_apply_kernel<<<BDN/256, 256>>>(kvr, kvr + MD, kvr + 2*MD, td, tf);

    gemm_kernel<<<grid, 256, GEMM_SMEM>>>(uh, wh + 3*DD, out, M_, D_, D_);
}

// round 9
// speedup vs baseline: 2.6439x; 1.1080x over previous
#include <cuda_runtime.h>
#include <cuda_fp16.h>
#include <cstdint>

// ---------------- problem constants ----------------
#define D_ 2048
#define B_ 4
#define T_ 2048
#define M_ (B_*T_)          // 8192

#define MD ((size_t)M_*(size_t)D_)   // 16,777,216
#define DD ((size_t)D_*(size_t)D_)   //  4,194,304

#define NCH 32
#define CL  (T_/NCH)                 // 64
#define BDN (B_*NCH*D_)              // 262,144

// ---------------- scratch (static device globals — allocation-free) --------
__device__ __align__(256) __half g_xh[3*MD];    // mixed activations (fp16)
__device__ __align__(256) __half g_wh[4*DD];    // weights (fp16)
__device__ __align__(256) float  g_kvr[3*MD];   // k, v, r (fp32 GEMM outputs)
__device__ __align__(256) __half g_uh[MD];      // wkv*sigmoid(r) (fp16)
__device__ __align__(256) float  g_agg[3*BDN];  // chunk aggregates
__device__ __align__(256) float  g_car[3*BDN];  // chunk carry-ins

// ---------------- weight -> fp16 ----------------
__global__ void wconv_kernel(const float* __restrict__ W0, const float* __restrict__ W1,
                             const float* __restrict__ W2, const float* __restrict__ W3)
{
    size_t i = (size_t)blockIdx.x * blockDim.x + threadIdx.x;
    if (i >= 4*DD) return;
    size_t which = i / DD;
    const float* Ws = (which == 0) ? W0 : (which == 1) ? W1 : (which == 2) ? W2 : W3;
    g_wh[i] = __float2half(Ws[i - which*DD]);
}

// ---------------- time-shift mix -> fp16 ----------------
__global__ void mix_kernel(const float* __restrict__ x,
                           const float* __restrict__ mk,
                           const float* __restrict__ mv,
                           const float* __restrict__ mr)
{
    size_t i = (size_t)blockIdx.x * blockDim.x + threadIdx.x;
    if (i >= MD) return;
    int d = (int)(i & (size_t)(D_-1));
    int t = (int)((i / D_) & (size_t)(T_-1));
    float xv = x[i];
    float lx = (t > 0) ? x[i - D_] : 0.0f;
    float dx = xv - lx;

    g_xh[i]        = __float2half(fmaf(dx, mk[d], lx));
    g_xh[MD + i]   = __float2half(fmaf(dx, mv[d], lx));
    g_xh[2*MD + i] = __float2half(fmaf(dx, mr[d], lx));
}

// ---------------- fp16 single-pass GEMM: C[M,N] = A[M,K] * B[N,K]^T ----------
// BK=64 (32 stages), 3-stage cp.async ring, register double-buffered
// ldmatrix fragments so smem latency overlaps MMA issue.
#define BM 128
#define BN 128
#define BK 64
#define NSTG 3
#define TILE_ELEMS (BM*BK)           // one operand tile (fp16 elems) = 8192
#define STAGE_ELEMS (2*TILE_ELEMS)   // A + B per stage
#define STAGE_BYTES (STAGE_ELEMS*2)  // 32768

__device__ __forceinline__ uint32_t cvta_s(const void* p) {
    return (uint32_t)__cvta_generic_to_shared(p);
}
__device__ __forceinline__ void cp16(uint32_t s, const void* g) {
    asm volatile("cp.async.cg.shared.global [%0], [%1], 16;\n" :: "r"(s), "l"(g));
}
// swizzled BYTE offset in a [128][64] fp16 tile (128B rows, 16B chunks)
__device__ __forceinline__ uint32_t swoff64(int r, int c) {
    return (uint32_t)(r*128 + ((c ^ (r & 7)) << 4));
}

#define MMA_FP16(cc, aa, bb)                                                    \
    asm volatile("mma.sync.aligned.m16n8k16.row.col.f32.f16.f16.f32 "            \
                 "{%0,%1,%2,%3},{%4,%5,%6,%7},{%8,%9},{%0,%1,%2,%3};\n"          \
                 : "+f"(cc[0]), "+f"(cc[1]), "+f"(cc[2]), "+f"(cc[3])            \
                 : "r"(aa[0]), "r"(aa[1]), "r"(aa[2]), "r"(aa[3]),               \
                   "r"(bb[0]), "r"(bb[1]))

#define LDSM4(dst, ad)                                                           \
    asm volatile("ldmatrix.sync.aligned.m8n8.x4.shared.b16 {%0,%1,%2,%3},[%4];\n"\
                 : "=r"((dst)[0]), "=r"((dst)[1]), "=r"((dst)[2]), "=r"((dst)[3])\
                 : "r"(ad))

__global__ void __launch_bounds__(256, 2)   // <=128 regs -> 2 CTAs/SM
gemm_kernel(const __half* __restrict__ Ah, const __half* __restrict__ Bh,
            float* __restrict__ C, int M, int N, int K)
{
    extern __shared__ __align__(16) char smem_raw[];
    const uint32_t sbase = cvta_s(smem_raw);

    const int tid  = threadIdx.x;
    const int lane = tid & 31;
    const int warp = tid >> 5;
    const int wm   = warp >> 2;   // 0..1  (64 rows each)
    const int wn   = warp & 3;    // 0..3  (32 cols each)

    const int bm = blockIdx.y * BM;
    const int bn = blockIdx.x * BN;

    float c[4][4][4];
    #pragma unroll
    for (int i = 0; i < 4; i++)
        #pragma unroll
        for (int j = 0; j < 4; j++)
            #pragma unroll
            for (int q = 0; q < 4; q++) c[i][j][q] = 0.0f;

    const __half* gbase[2] = { Ah + (size_t)bm*K, Bh + (size_t)bn*K };

    // ---- precomputed per-warp ldmatrix addressing -------------------------
    // A frag (mt):  row = wm*64 + mt*16 + (lane&15); chunk = kk*2 + (lane>>4)
    // B frag (p):   row = wn*32 + p*16  + (lane&15); chunk = kk*2 + (lane>>4)
    // +16 rows leaves (row&7) unchanged -> swizzle XOR constant per warp/lane.
    const int rA = wm*64 + (lane & 15);
    const int rB = wn*32 + (lane & 15);
    const int hi = lane >> 4;
    uint32_t aAddr0 = sbase + (uint32_t)(rA*128);                 // A tile at +0
    uint32_t bAddr0 = sbase + (uint32_t)(TILE_ELEMS*2 + rB*128);  // B tile at +16KB
    uint32_t chA[4], chB[4];
    #pragma unroll
    for (int kk = 0; kk < 4; kk++) {
        chA[kk] = (uint32_t)(((kk*2 + hi) ^ (rA & 7)) << 4);
        chB[kk] = (uint32_t)(((kk*2 + hi) ^ (rB & 7)) << 4);
    }

    auto issue_loads = [&](int s, int bi) {
        const int k0 = s * BK;
        const uint32_t st = sbase + (uint32_t)bi * STAGE_BYTES;
        #pragma unroll
        for (int q = 0; q < 8; q++) {
            int cid = tid + q*256;              // 2048 16B-chunks per stage
            int op  = cid >> 10;                // 0..1
            int wi  = cid & 1023;
            int rr  = wi >> 3, cc = wi & 7;
            cp16(st + (uint32_t)op*(TILE_ELEMS*2) + swoff64(rr, cc),
                 gbase[op] + (size_t)rr*K + k0 + cc*8);
        }
        asm volatile("cp.async.commit_group;\n");
    };

    auto compute_stage = [&](int bi) {
        const uint32_t so = (uint32_t)bi * STAGE_BYTES;
        const uint32_t aB = aAddr0 + so;
        const uint32_t bB = bAddr0 + so;

        uint32_t bhf[2][4][2];   // [buf][nt][2]
        uint32_t af[2][4];       // [buf][4] (covers mt rows 0..15 of 64-row strip)

        // preload kk=0 fragments
        {
            uint32_t t0[4], t1[4];
            LDSM4(t0, bB + chB[0]);            // p=0 -> nt 0,1
            LDSM4(t1, bB + 2048 + chB[0]);     // p=1 -> nt 2,3
            bhf[0][0][0]=t0[0]; bhf[0][0][1]=t0[2];
            bhf[0][1][0]=t0[1]; bhf[0][1][1]=t0[3];
            bhf[0][2][0]=t1[0]; bhf[0][2][1]=t1[2];
            bhf[0][3][0]=t1[1]; bhf[0][3][1]=t1[3];
            LDSM4(af[0], aB + chA[0]);         // mt=0
        }

        #pragma unroll
        for (int kk = 0; kk < 4; kk++) {
            const int cb = kk & 1;
            #pragma unroll
            for (int mt = 0; mt < 4; mt++) {
                const int ca = mt & 1;
                // prefetch next fragment(s) before consuming current
                if (mt < 3) {
                    LDSM4(af[ca^1], aB + (uint32_t)((mt+1)*2048) + chA[kk]);
                } else if (kk < 3) {
                    uint32_t t0[4], t1[4];
                    LDSM4(t0, bB + chB[kk+1]);
                    LDSM4(t1, bB + 2048 + chB[kk+1]);
                    bhf[cb^1][0][0]=t0[0]; bhf[cb^1][0][1]=t0[2];
                    bhf[cb^1][1][0]=t0[1]; bhf[cb^1][1][1]=t0[3];
                    bhf[cb^1][2][0]=t1[0]; bhf[cb^1][2][1]=t1[2];
                    bhf[cb^1][3][0]=t1[1]; bhf[cb^1][3][1]=t1[3];
                    LDSM4(af[ca^1], aB + chA[kk+1]);
                }
                #pragma unroll
                for (int nt = 0; nt < 4; nt++)
                    MMA_FP16(c[mt][nt], af[ca], bhf[cb][nt]);
            }
        }
    };

    const int NS = K / BK;                     // 32 stages
    issue_loads(0, 0);
    issue_loads(1, 1);

    for (int s = 0; s < NS; s++) {
        const int bi = s % NSTG;
        if (s + 1 < NS) asm volatile("cp.async.wait_group 1;\n" ::: "memory");
        else            asm volatile("cp.async.wait_group 0;\n" ::: "memory");
        __syncthreads();
        if (s + 2 < NS) issue_loads(s + 2, (s + 2) % NSTG);
        compute_stage(bi);
    }

    // epilogue
    #pragma unroll
    for (int mt = 0; mt < 4; mt++) {
        #pragma unroll
        for (int nt = 0; nt < 4; nt++) {
            int row = bm + wm*64 + mt*16 + (lane >> 2);
            int col = bn + wn*32 + nt*8 + (lane & 3)*2;
            *reinterpret_cast<float2*>(C + (size_t)row*N + col) =
                make_float2(c[mt][nt][0], c[mt][nt][1]);
            *reinterpret_cast<float2*>(C + (size_t)(row+8)*N + col) =
                make_float2(c[mt][nt][2], c[mt][nt][3]);
        }
    }
}

// ============================================================================
// WKV parallel scan: 3 phases (linear recurrence on unnormalized state).
// ============================================================================

__global__ void wkv_chunk_kernel(const float* __restrict__ kk, const float* __restrict__ vv,
                                 const float* __restrict__ td)
{
    int g  = blockIdx.x * 256 + threadIdx.x;    // 0 .. BDN-1
    int d  = g & (D_-1);
    int ch = (g >> 11) & (NCH-1);
    int b  = g >> 16;
    float w = expf(td[d]);

    float alpha = 0.0f, beta = 0.0f, eps = -1e30f;
    size_t base = ((size_t)b * T_ + (size_t)ch * CL) * D_ + d;

    #pragma unroll 4
    for (int i = 0; i < CL; i++) {
        size_t idx = base + (size_t)i * D_;
        float kt = kk[idx];
        float vt = vv[idx];
        float ww2  = eps - w;
        float tau2 = fmaxf(ww2, kt);
        float e1b  = __expf(ww2 - tau2);
        float e2b  = __expf(kt - tau2);
        alpha = e1b*alpha + e2b*vt;
        beta  = e1b*beta + e2b;
        eps   = tau2;
    }
    size_t o = ((size_t)b * NCH + ch) * D_ + d;
    g_agg[o]         = alpha;
    g_agg[BDN + o]   = beta;
    g_agg[2*BDN + o] = eps;
}

__global__ void wkv_stitch_kernel(const float* __restrict__ td)
{
    int g = blockIdx.x * 256 + threadIdx.x;     // 0 .. B_*D_-1
    int d = g & (D_-1);
    int b = g >> 11;
    float w  = expf(td[d]);
    float dl = -w * (float)CL;                  // log decay across one chunk

    float a = 0.0f, bt = 0.0f, e = -1e30f;
    #pragma unroll 4
    for (int ch = 0; ch < NCH; ch++) {
        size_t o = ((size_t)b * NCH + ch) * D_ + d;
        g_car[o]         = a;
        g_car[BDN + o]   = bt;
        g_car[2*BDN + o] = e;
        float pa = g_agg[o];
        float pb = g_agg[BDN + o];
        float pe = g_agg[2*BDN + o];
        float ein = e + dl;
        float ne  = fmaxf(ein, pe);
        float f1  = __expf(ein - ne);
        float f2  = __expf(pe - ne);
        a  = f1*a  + f2*pa;
        bt = f1*bt + f2*pb;
        e  = ne;
    }
}

__global__ void wkv_apply_kernel(const float* __restrict__ kk, const float* __restrict__ vv,
                                 const float* __restrict__ rr,
                                 const float* __restrict__ td, const float* __restrict__ tf)
{
    int g  = blockIdx.x * 256 + threadIdx.x;
    int d  = g & (D_-1);
    int ch = (g >> 11) & (NCH-1);
    int b  = g >> 16;
    float w = expf(td[d]);
    float u = tf[d];

    size_t o = ((size_t)b * NCH + ch) * D_ + d;
    float alpha = g_car[o];
    float beta  = g_car[BDN + o];
    float eps   = g_car[2*BDN + o];

    size_t base = ((size_t)b * T_ + (size_t)ch * CL) * D_ + d;

    #pragma unroll 4
    for (int i = 0; i < CL; i++) {
        size_t idx = base + (size_t)i * D_;
        float kt = kk[idx];
        float vt = vv[idx];
        float rt = rr[idx];

        float ww  = u + kt;
        float tau = fmaxf(eps, ww);
        float e1  = __expf(eps - tau);
        float e2  = __expf(ww - tau);
        float out = (e1*alpha + e2*vt) / (e1*beta + e2);

        float ww2  = eps - w;
        float tau2 = fmaxf(ww2, kt);
        float e1b  = __expf(ww2 - tau2);
        float e2b  = __expf(kt - tau2);
        alpha = e1b*alpha + e2b*vt;
        beta  = e1b*beta + e2b;
        eps   = tau2;

        float sr = 1.0f / (1.0f + __expf(-rt));
        g_uh[idx] = __float2half(out * sr);
    }
}

// ---------------- launch ----------------
extern "C" void kernel_launch(void* const* d_in, const int* in_sizes, int n_in,
                              void* d_out, int out_size)
{
    const float* x  = (const float*)d_in[0];
    const float* td = (const float*)d_in[1];
    const float* tf = (const float*)d_in[2];
    const float* mk = (const float*)d_in[3];
    const float* mv = (const float*)d_in[4];
    const float* mr = (const float*)d_in[5];
    const float* Wk = (const float*)d_in[6];
    const float* Wv = (const float*)d_in[7];
    const float* Wr = (const float*)d_in[8];
    const float* Wo = (const float*)d_in[9];
    float* out = (float*)d_out;

    __half *xh, *wh, *uh;
    float* kvr;
    cudaGetSymbolAddress((void**)&xh,  g_xh);
    cudaGetSymbolAddress((void**)&wh,  g_wh);
    cudaGetSymbolAddress((void**)&kvr, g_kvr);
    cudaGetSymbolAddress((void**)&uh,  g_uh);

    const int GEMM_SMEM = NSTG * STAGE_BYTES;  // 98304
    cudaFuncSetAttribute(gemm_kernel, cudaFuncAttributeMaxDynamicSharedMemorySize, GEMM_SMEM);

    wconv_kernel<<<(unsigned)((4*DD + 255) / 256), 256>>>(Wk, Wv, Wr, Wo);
    mix_kernel<<<(unsigned)((MD + 255) / 256), 256>>>(x, mk, mv, mr);

    dim3 grid(D_ / BN, M_ / BM);   // (16, 64)
    for (int i = 0; i < 3; i++) {
        gemm_kernel<<<grid, 256, GEMM_SMEM>>>(xh + (size_t)i*MD,
                                              wh + (size_t)i*DD,
                                              kvr + (size_t)i*MD, M_, D_, D_);
    }

    wkv_chunk_kernel<<<BDN/256, 256>>>(kvr, kvr + MD, td);
    wkv_stitch_kernel<<<(B_*D_)/256, 256>>>(td);
    wkv_apply_kernel<<<BDN/256, 256>>>(kvr, kvr + MD, kvr + 2*MD, td, tf);

    gemm_kernel<<<grid, 256, GEMM_SMEM>>>(uh, wh + 3*DD, out, M_, D_, D_);
}

// round 10
// speedup vs baseline: 2.6585x; 1.0055x over previous
#include <cuda_runtime.h>
#include <cuda_fp16.h>
#include <cstdint>

// ---------------- problem constants ----------------
#define D_ 2048
#define B_ 4
#define T_ 2048
#define M_ (B_*T_)          // 8192

#define MD ((size_t)M_*(size_t)D_)   // 16,777,216
#define DD ((size_t)D_*(size_t)D_)   //  4,194,304

#define NCH 32
#define CL  (T_/NCH)                 // 64
#define BDN (B_*NCH*D_)              // 262,144

// ---------------- scratch (static device globals — allocation-free) --------
__device__ __align__(256) __half g_xh[3*MD];    // mixed activations (fp16)
__device__ __align__(256) __half g_wh[4*DD];    // weights (fp16)
__device__ __align__(256) float  g_kvr[3*MD];   // k, v, r (fp32 GEMM outputs)
__device__ __align__(256) __half g_uh[MD];      // wkv*sigmoid(r) (fp16)
__device__ __align__(256) float  g_agg[3*BDN];  // chunk aggregates
__device__ __align__(256) float  g_car[3*BDN];  // chunk carry-ins

// ---------------- weight -> fp16 ----------------
__global__ void wconv_kernel(const float* __restrict__ W0, const float* __restrict__ W1,
                             const float* __restrict__ W2, const float* __restrict__ W3)
{
    size_t i = (size_t)blockIdx.x * blockDim.x + threadIdx.x;
    if (i >= 4*DD) return;
    size_t which = i / DD;
    const float* Ws = (which == 0) ? W0 : (which == 1) ? W1 : (which == 2) ? W2 : W3;
    g_wh[i] = __float2half(Ws[i - which*DD]);
}

// ---------------- time-shift mix -> fp16 ----------------
__global__ void mix_kernel(const float* __restrict__ x,
                           const float* __restrict__ mk,
                           const float* __restrict__ mv,
                           const float* __restrict__ mr)
{
    size_t i = (size_t)blockIdx.x * blockDim.x + threadIdx.x;
    if (i >= MD) return;
    int d = (int)(i & (size_t)(D_-1));
    int t = (int)((i / D_) & (size_t)(T_-1));
    float xv = x[i];
    float lx = (t > 0) ? x[i - D_] : 0.0f;
    float dx = xv - lx;

    g_xh[i]        = __float2half(fmaf(dx, mk[d], lx));
    g_xh[MD + i]   = __float2half(fmaf(dx, mv[d], lx));
    g_xh[2*MD + i] = __float2half(fmaf(dx, mr[d], lx));
}

// ---------------- fp16 single-pass GEMM: C[M,N] = A[M,K] * B[N,K]^T ----------
// BK=64 (32 stages), 3-stage cp.async ring. Fragments software-pipelined at
// kk granularity: all LDSM for chunk kk+1 issued before the 16 MMAs of kk,
// giving ~100cy prefetch distance >> 29cy LDSM latency.
#define BM 128
#define BN 128
#define BK 64
#define NSTG 3
#define TILE_ELEMS (BM*BK)           // one operand tile (fp16 elems) = 8192
#define STAGE_ELEMS (2*TILE_ELEMS)   // A + B per stage
#define STAGE_BYTES (STAGE_ELEMS*2)  // 32768

__device__ __forceinline__ uint32_t cvta_s(const void* p) {
    return (uint32_t)__cvta_generic_to_shared(p);
}
__device__ __forceinline__ void cp16(uint32_t s, const void* g) {
    asm volatile("cp.async.cg.shared.global [%0], [%1], 16;\n" :: "r"(s), "l"(g));
}
// swizzled BYTE offset in a [128][64] fp16 tile (128B rows, 16B chunks)
__device__ __forceinline__ uint32_t swoff64(int r, int c) {
    return (uint32_t)(r*128 + ((c ^ (r & 7)) << 4));
}

#define MMA_FP16(cc, aa, bb)                                                    \
    asm volatile("mma.sync.aligned.m16n8k16.row.col.f32.f16.f16.f32 "            \
                 "{%0,%1,%2,%3},{%4,%5,%6,%7},{%8,%9},{%0,%1,%2,%3};\n"          \
                 : "+f"(cc[0]), "+f"(cc[1]), "+f"(cc[2]), "+f"(cc[3])            \
                 : "r"(aa[0]), "r"(aa[1]), "r"(aa[2]), "r"(aa[3]),               \
                   "r"(bb[0]), "r"(bb[1]))

#define LDSM4(dst, ad)                                                           \
    asm volatile("ldmatrix.sync.aligned.m8n8.x4.shared.b16 {%0,%1,%2,%3},[%4];\n"\
                 : "=r"((dst)[0]), "=r"((dst)[1]), "=r"((dst)[2]), "=r"((dst)[3])\
                 : "r"(ad))

__global__ void __launch_bounds__(256, 2)   // <=128 regs -> 2 CTAs/SM
gemm_kernel(const __half* __restrict__ Ah, const __half* __restrict__ Bh,
            float* __restrict__ C, int M, int N, int K)
{
    extern __shared__ __align__(16) char smem_raw[];
    const uint32_t sbase = cvta_s(smem_raw);

    const int tid  = threadIdx.x;
    const int lane = tid & 31;
    const int warp = tid >> 5;
    const int wm   = warp >> 2;   // 0..1  (64 rows each)
    const int wn   = warp & 3;    // 0..3  (32 cols each)

    const int bm = blockIdx.y * BM;
    const int bn = blockIdx.x * BN;

    float c[4][4][4];
    #pragma unroll
    for (int i = 0; i < 4; i++)
        #pragma unroll
        for (int j = 0; j < 4; j++)
            #pragma unroll
            for (int q = 0; q < 4; q++) c[i][j][q] = 0.0f;

    const __half* gbase[2] = { Ah + (size_t)bm*K, Bh + (size_t)bn*K };

    // ---- precomputed per-warp ldmatrix addressing -------------------------
    const int rA = wm*64 + (lane & 15);
    const int rB = wn*32 + (lane & 15);
    const int hi = lane >> 4;
    uint32_t aAddr0 = sbase + (uint32_t)(rA*128);                 // A tile at +0
    uint32_t bAddr0 = sbase + (uint32_t)(TILE_ELEMS*2 + rB*128);  // B tile at +16KB
    uint32_t chA[4], chB[4];
    #pragma unroll
    for (int kk = 0; kk < 4; kk++) {
        chA[kk] = (uint32_t)(((kk*2 + hi) ^ (rA & 7)) << 4);
        chB[kk] = (uint32_t)(((kk*2 + hi) ^ (rB & 7)) << 4);
    }

    auto issue_loads = [&](int s, int bi) {
        const int k0 = s * BK;
        const uint32_t st = sbase + (uint32_t)bi * STAGE_BYTES;
        #pragma unroll
        for (int q = 0; q < 8; q++) {
            int cid = tid + q*256;              // 2048 16B-chunks per stage
            int op  = cid >> 10;                // 0..1
            int wi  = cid & 1023;
            int rr  = wi >> 3, cc = wi & 7;
            cp16(st + (uint32_t)op*(TILE_ELEMS*2) + swoff64(rr, cc),
                 gbase[op] + (size_t)rr*K + k0 + cc*8);
        }
        asm volatile("cp.async.commit_group;\n");
    };

    auto compute_stage = [&](int bi) {
        const uint32_t so = (uint32_t)bi * STAGE_BYTES;
        const uint32_t aB = aAddr0 + so;
        const uint32_t bB = bAddr0 + so;

        uint32_t af[2][4][4];    // [buf][mt][4]
        uint32_t bf[2][4][2];    // [buf][nt][2]

        // preload all fragments for kk=0
        {
            uint32_t t0[4], t1[4];
            LDSM4(t0, bB + chB[0]);
            LDSM4(t1, bB + 2048 + chB[0]);
            bf[0][0][0]=t0[0]; bf[0][0][1]=t0[2];
            bf[0][1][0]=t0[1]; bf[0][1][1]=t0[3];
            bf[0][2][0]=t1[0]; bf[0][2][1]=t1[2];
            bf[0][3][0]=t1[1]; bf[0][3][1]=t1[3];
            #pragma unroll
            for (int mt = 0; mt < 4; mt++)
                LDSM4(af[0][mt], aB + (uint32_t)(mt*2048) + chA[0]);
        }

        #pragma unroll
        for (int kk = 0; kk < 4; kk++) {
            const int cb = kk & 1;
            // prefetch ALL fragments for kk+1 before consuming kk
            if (kk < 3) {
                uint32_t t0[4], t1[4];
                LDSM4(t0, bB + chB[kk+1]);
                LDSM4(t1, bB + 2048 + chB[kk+1]);
                bf[cb^1][0][0]=t0[0]; bf[cb^1][0][1]=t0[2];
                bf[cb^1][1][0]=t0[1]; bf[cb^1][1][1]=t0[3];
                bf[cb^1][2][0]=t1[0]; bf[cb^1][2][1]=t1[2];
                bf[cb^1][3][0]=t1[1]; bf[cb^1][3][1]=t1[3];
                #pragma unroll
                for (int mt = 0; mt < 4; mt++)
                    LDSM4(af[cb^1][mt], aB + (uint32_t)(mt*2048) + chA[kk+1]);
            }
            #pragma unroll
            for (int mt = 0; mt < 4; mt++)
                #pragma unroll
                for (int nt = 0; nt < 4; nt++)
                    MMA_FP16(c[mt][nt], af[cb][mt], bf[cb][nt]);
        }
    };

    const int NS = K / BK;                     // 32 stages
    issue_loads(0, 0);
    issue_loads(1, 1);

    for (int s = 0; s < NS; s++) {
        const int bi = s % NSTG;
        if (s + 1 < NS) asm volatile("cp.async.wait_group 1;\n" ::: "memory");
        else            asm volatile("cp.async.wait_group 0;\n" ::: "memory");
        __syncthreads();
        if (s + 2 < NS) issue_loads(s + 2, (s + 2) % NSTG);
        compute_stage(bi);
    }

    // epilogue
    #pragma unroll
    for (int mt = 0; mt < 4; mt++) {
        #pragma unroll
        for (int nt = 0; nt < 4; nt++) {
            int row = bm + wm*64 + mt*16 + (lane >> 2);
            int col = bn + wn*32 + nt*8 + (lane & 3)*2;
            *reinterpret_cast<float2*>(C + (size_t)row*N + col) =
                make_float2(c[mt][nt][0], c[mt][nt][1]);
            *reinterpret_cast<float2*>(C + (size_t)(row+8)*N + col) =
                make_float2(c[mt][nt][2], c[mt][nt][3]);
        }
    }
}

// ============================================================================
// WKV parallel scan: 3 phases (linear recurrence on unnormalized state).
// ============================================================================

__global__ void wkv_chunk_kernel(const float* __restrict__ kk, const float* __restrict__ vv,
                                 const float* __restrict__ td)
{
    int g  = blockIdx.x * 256 + threadIdx.x;    // 0 .. BDN-1
    int d  = g & (D_-1);
    int ch = (g >> 11) & (NCH-1);
    int b  = g >> 16;
    float w = expf(td[d]);

    float alpha = 0.0f, beta = 0.0f, eps = -1e30f;
    size_t base = ((size_t)b * T_ + (size_t)ch * CL) * D_ + d;

    #pragma unroll 4
    for (int i = 0; i < CL; i++) {
        size_t idx = base + (size_t)i * D_;
        float kt = kk[idx];
        float vt = vv[idx];
        float ww2  = eps - w;
        float tau2 = fmaxf(ww2, kt);
        float e1b  = __expf(ww2 - tau2);
        float e2b  = __expf(kt - tau2);
        alpha = e1b*alpha + e2b*vt;
        beta  = e1b*beta + e2b;
        eps   = tau2;
    }
    size_t o = ((size_t)b * NCH + ch) * D_ + d;
    g_agg[o]         = alpha;
    g_agg[BDN + o]   = beta;
    g_agg[2*BDN + o] = eps;
}

__global__ void wkv_stitch_kernel(const float* __restrict__ td)
{
    int g = blockIdx.x * 256 + threadIdx.x;     // 0 .. B_*D_-1
    int d = g & (D_-1);
    int b = g >> 11;
    float w  = expf(td[d]);
    float dl = -w * (float)CL;                  // log decay across one chunk

    float a = 0.0f, bt = 0.0f, e = -1e30f;
    #pragma unroll 4
    for (int ch = 0; ch < NCH; ch++) {
        size_t o = ((size_t)b * NCH + ch) * D_ + d;
        g_car[o]         = a;
        g_car[BDN + o]   = bt;
        g_car[2*BDN + o] = e;
        float pa = g_agg[o];
        float pb = g_agg[BDN + o];
        float pe = g_agg[2*BDN + o];
        float ein = e + dl;
        float ne  = fmaxf(ein, pe);
        float f1  = __expf(ein - ne);
        float f2  = __expf(pe - ne);
        a  = f1*a  + f2*pa;
        bt = f1*bt + f2*pb;
        e  = ne;
    }
}

__global__ void wkv_apply_kernel(const float* __restrict__ kk, const float* __restrict__ vv,
                                 const float* __restrict__ rr,
                                 const float* __restrict__ td, const float* __restrict__ tf)
{
    int g  = blockIdx.x * 256 + threadIdx.x;
    int d  = g & (D_-1);
    int ch = (g >> 11) & (NCH-1);
    int b  = g >> 16;
    float w = expf(td[d]);
    float u = tf[d];

    size_t o = ((size_t)b * NCH + ch) * D_ + d;
    float alpha = g_car[o];
    float beta  = g_car[BDN + o];
    float eps   = g_car[2*BDN + o];

    size_t base = ((size_t)b * T_ + (size_t)ch * CL) * D_ + d;

    #pragma unroll 4
    for (int i = 0; i < CL; i++) {
        size_t idx = base + (size_t)i * D_;
        float kt = kk[idx];
        float vt = vv[idx];
        float rt = rr[idx];

        float ww  = u + kt;
        float tau = fmaxf(eps, ww);
        float e1  = __expf(eps - tau);
        float e2  = __expf(ww - tau);
        float out = (e1*alpha + e2*vt) / (e1*beta + e2);

        float ww2  = eps - w;
        float tau2 = fmaxf(ww2, kt);
        float e1b  = __expf(ww2 - tau2);
        float e2b  = __expf(kt - tau2);
        alpha = e1b*alpha + e2b*vt;
        beta  = e1b*beta + e2b;
        eps   = tau2;

        float sr = 1.0f / (1.0f + __expf(-rt));
        g_uh[idx] = __float2half(out * sr);
    }
}

// ---------------- launch ----------------
extern "C" void kernel_launch(void* const* d_in, const int* in_sizes, int n_in,
                              void* d_out, int out_size)
{
    const float* x  = (const float*)d_in[0];
    const float* td = (const float*)d_in[1];
    const float* tf = (const float*)d_in[2];
    const float* mk = (const float*)d_in[3];
    const float* mv = (const float*)d_in[4];
    const float* mr = (const float*)d_in[5];
    const float* Wk = (const float*)d_in[6];
    const float* Wv = (const float*)d_in[7];
    const float* Wr = (const float*)d_in[8];
    const float* Wo = (const float*)d_in[9];
    float* out = (float*)d_out;

    __half *xh, *wh, *uh;
    float* kvr;
    cudaGetSymbolAddress((void**)&xh,  g_xh);
    cudaGetSymbolAddress((void**)&wh,  g_wh);
    cudaGetSymbolAddress((void**)&kvr, g_kvr);
    cudaGetSymbolAddress((void**)&uh,  g_uh);

    const int GEMM_SMEM = NSTG * STAGE_BYTES;  // 98304
    cudaFuncSetAttribute(gemm_kernel, cudaFuncAttributeMaxDynamicSharedMemorySize, GEMM_SMEM);

    wconv_kernel<<<(unsigned)((4*DD + 255) / 256), 256>>>(Wk, Wv, Wr, Wo);
    mix_kernel<<<(unsigned)((MD + 255) / 256), 256>>>(x, mk, mv, mr);

    dim3 grid(D_ / BN, M_ / BM);   // (16, 64)
    for (int i = 0; i < 3; i++) {
        gemm_kernel<<<grid, 256, GEMM_SMEM>>>(xh + (size_t)i*MD,
                                              wh + (size_t)i*DD,
                                              kvr + (size_t)i*MD, M_, D_, D_);
    }

    wkv_chunk_kernel<<<BDN/256, 256>>>(kvr, kvr + MD, td);
    wkv_stitch_kernel<<<(B_*D_)/256, 256>>>(td);
    wkv_apply_kernel<<<BDN/256, 256>>>(kvr, kvr + MD, kvr + 2*MD, td, tf);

    gemm_kernel<<<grid, 256, GEMM_SMEM>>>(uh, wh + 3*DD, out, M_, D_, D_);
}